// round 2
// baseline (speedup 1.0000x reference)
#include <cuda_runtime.h>
#include <math.h>
#include <stdint.h>

// GAT fused pipeline for GNNModel_74801150427817  (round 2: no-max softmax,
// deferred normalization, vector RED atomics)
//
//   h = x @ W                        [N,128] fp32 SGEMM, W resident in smem
//   a_src/a_dst fused in GEMM epilogue
//   passA: w = exp(lrelu(a_src[s]+a_dst[d])), esum[d] += w   (vector RED)
//   passB: agg[d] += h[s] * w                                 (vector RED)
//   final: (agg/esum) + bias -> relu -> fc dot -> sigmoid
//
// Shapes fixed by dataset: N=500000, E=1500000, C_IN=128, H=4, OUT=32.

#define CIN   128
#define HOUT  128              // H*OUT
#define HEADS 4
#define NMAX  500000
#define EMAX  1500000
#define ETOTMAX (EMAX + NMAX)
#define NEG_SLOPE 0.2f

// ---------------- scratch (device globals; no allocation allowed) ----------
__device__ float  g_h   [(size_t)NMAX * HOUT];   // 256 MB
__device__ float  g_agg [(size_t)NMAX * HOUT];   // 256 MB
__device__ float  g_asrc[NMAX * HEADS];
__device__ float  g_adst[NMAX * HEADS];
__device__ float  g_esum[NMAX * HEADS];
__device__ float4 g_w   [ETOTMAX];               // 32 MB edge weights
__device__ int    g_is64;

// ---------------- helpers --------------------------------------------------
__device__ __forceinline__ float lrelu(float v) {
    return v > 0.f ? v : NEG_SLOPE * v;
}

__device__ __forceinline__ int edge_idx(const int* p, int i, int is64) {
    return is64 ? p[2 * i] : p[i];
}

// sm_90+ vectorized reduction: one RED for 4 consecutive floats
__device__ __forceinline__ void red_add_v4(float* addr, float a, float b,
                                           float c, float d) {
    asm volatile("red.global.add.v4.f32 [%0], {%1,%2,%3,%4};"
                 :: "l"(addr), "f"(a), "f"(b), "f"(c), "f"(d) : "memory");
}

// ---------------- 0) int32/int64 edge-index detection ----------------------
__global__ void detect_kernel(const int* __restrict__ ei) {
    __shared__ int anynz;
    if (threadIdx.x == 0) anynz = 0;
    __syncthreads();
    // int64 little-endian with values < 2^31 => every odd 32-bit word is 0
    if (ei[2 * threadIdx.x + 1] != 0) atomicOr(&anynz, 1);
    __syncthreads();
    if (threadIdx.x == 0) g_is64 = anynz ? 0 : 1;
}

// ---------------- 1) init accumulators -------------------------------------
__global__ void init_kernel(int N) {
    int stride = gridDim.x * blockDim.x;
    int gid = blockIdx.x * blockDim.x + threadIdx.x;
    float4 z4 = make_float4(0.f, 0.f, 0.f, 0.f);
    for (int i = gid; i < N * 32; i += stride)     // agg = N*32 float4
        ((float4*)g_agg)[i] = z4;
    for (int i = gid; i < N; i += stride)          // esum = N float4
        ((float4*)g_esum)[i] = z4;
}

// ---------------- 2) SGEMM h = x @ W with fused attention dots --------------
// 256 threads, 64 rows of x per block, full 128 cols, K=128 single shot.
// smem: W resident [128][128] (64KB) + x tile transposed [128][65] (~33KB)
#define GEMM_ROWS 64
#define SX_LD 65

__global__ __launch_bounds__(256, 2)
void gemm_att_kernel(const float* __restrict__ x,
                     const float* __restrict__ W,
                     const float* __restrict__ att_src,
                     const float* __restrict__ att_dst,
                     int N) {
    extern __shared__ float smem[];
    float* sW = smem;                 // [k*128 + c]
    float* sX = smem + CIN * HOUT;    // [k*SX_LD + r]

    const int t = threadIdx.x;
    const int block_row = blockIdx.x * GEMM_ROWS;

    for (int i = t; i < CIN * HOUT / 4; i += 256)
        ((float4*)sW)[i] = ((const float4*)W)[i];

    for (int i = t; i < GEMM_ROWS * 32; i += 256) {
        int r  = i >> 5;
        int kq = i & 31;
        int row = block_row + r;
        float4 v = make_float4(0.f, 0.f, 0.f, 0.f);
        if (row < N)
            v = ((const float4*)(x + (size_t)row * CIN))[kq];
        sX[(4 * kq + 0) * SX_LD + r] = v.x;
        sX[(4 * kq + 1) * SX_LD + r] = v.y;
        sX[(4 * kq + 2) * SX_LD + r] = v.z;
        sX[(4 * kq + 3) * SX_LD + r] = v.w;
    }
    __syncthreads();

    const int tx = t & 31;   // cols 4*tx..4*tx+3
    const int ty = t >> 5;   // rows 8*ty..8*ty+7

    float acc[8][4];
#pragma unroll
    for (int r = 0; r < 8; r++)
#pragma unroll
        for (int c = 0; c < 4; c++) acc[r][c] = 0.f;

#pragma unroll 4
    for (int k = 0; k < CIN; k++) {
        float4 b = *(const float4*)&sW[k * HOUT + 4 * tx];
        float a[8];
#pragma unroll
        for (int r = 0; r < 8; r++) a[r] = sX[k * SX_LD + 8 * ty + r];
#pragma unroll
        for (int r = 0; r < 8; r++) {
            acc[r][0] = fmaf(a[r], b.x, acc[r][0]);
            acc[r][1] = fmaf(a[r], b.y, acc[r][1]);
            acc[r][2] = fmaf(a[r], b.z, acc[r][2]);
            acc[r][3] = fmaf(a[r], b.w, acc[r][3]);
        }
    }

    // epilogue: store h + per-head attention dots (width-8 shuffle tree)
    float4 avs = ((const float4*)att_src)[tx];
    float4 avd = ((const float4*)att_dst)[tx];
#pragma unroll
    for (int r = 0; r < 8; r++) {
        int row = block_row + 8 * ty + r;
        float ps = acc[r][0] * avs.x + acc[r][1] * avs.y +
                   acc[r][2] * avs.z + acc[r][3] * avs.w;
        float pd = acc[r][0] * avd.x + acc[r][1] * avd.y +
                   acc[r][2] * avd.z + acc[r][3] * avd.w;
#pragma unroll
        for (int off = 4; off >= 1; off >>= 1) {
            ps += __shfl_down_sync(0xffffffffu, ps, off, 8);
            pd += __shfl_down_sync(0xffffffffu, pd, off, 8);
        }
        if (row < N) {
            ((float4*)(g_h + (size_t)row * HOUT))[tx] =
                make_float4(acc[r][0], acc[r][1], acc[r][2], acc[r][3]);
            if ((tx & 7) == 0) {
                int head = tx >> 3;
                g_asrc[row * HEADS + head] = ps;
                g_adst[row * HEADS + head] = pd;
            }
        }
    }
}

// ---------------- 3) pass A: w = exp(lrelu(as+ad)); esum[d] += w ------------
// (softmax is shift-invariant; e in [-7,7] so exp() is fp32-safe without max)
__global__ void edge_passA(const int* __restrict__ ei, int E, int N) {
    int i = blockIdx.x * blockDim.x + threadIdx.x;
    int Etot = E + N;
    if (i >= Etot) return;
    const int is64 = g_is64;
    int s, d;
    if (i < E) { s = edge_idx(ei, i, is64); d = edge_idx(ei, E + i, is64); }
    else       { s = d = i - E; }
    float4 as = ((const float4*)g_asrc)[s];
    float4 ad = ((const float4*)g_adst)[d];
    float4 w = make_float4(__expf(lrelu(as.x + ad.x)),
                           __expf(lrelu(as.y + ad.y)),
                           __expf(lrelu(as.z + ad.z)),
                           __expf(lrelu(as.w + ad.w)));
    g_w[i] = w;
    red_add_v4(&g_esum[d * HEADS], w.x, w.y, w.z, w.w);
}

// ---------------- 4) pass B: agg[d] += h[s] * w  (unnormalized) -------------
// one warp per edge; lane owns 4 consecutive channels
__global__ __launch_bounds__(256)
void edge_passB(const int* __restrict__ ei, int E, int N) {
    int gw   = (blockIdx.x * blockDim.x + threadIdx.x) >> 5;
    int lane = threadIdx.x & 31;
    int Etot = E + N;
    if (gw >= Etot) return;
    const int is64 = g_is64;
    int s, d;
    if (gw < E) { s = edge_idx(ei, gw, is64); d = edge_idx(ei, E + gw, is64); }
    else        { s = d = gw - E; }
    float4 w = g_w[gw];
    int head = lane >> 3;
    float wl = (head == 0) ? w.x : (head == 1) ? w.y : (head == 2) ? w.z : w.w;

    float4 hv = ((const float4*)(g_h + (size_t)s * HOUT))[lane];
    red_add_v4(g_agg + (size_t)d * HOUT + 4 * lane,
               hv.x * wl, hv.y * wl, hv.z * wl, hv.w * wl);
}

// ---------------- 5) final: normalize, +bias, relu, fc dot, sigmoid ---------
__global__ __launch_bounds__(256)
void final_kernel(const float* __restrict__ bias,
                  const float* __restrict__ fc_w,
                  const float* __restrict__ fc_b,
                  float* __restrict__ out, int N) {
    int node = (blockIdx.x * blockDim.x + threadIdx.x) >> 5;
    int lane = threadIdx.x & 31;
    if (node >= N) return;
    float4 sm = ((const float4*)g_esum)[node];   // warp-broadcast load
    int head = lane >> 3;
    float inv = 1.f / ((head == 0) ? sm.x : (head == 1) ? sm.y
                       : (head == 2) ? sm.z : sm.w);
    float4 a = ((const float4*)(g_agg + (size_t)node * HOUT))[lane];
    float4 b = ((const float4*)bias)[lane];
    float4 v = make_float4(fmaxf(a.x * inv + b.x, 0.f),
                           fmaxf(a.y * inv + b.y, 0.f),
                           fmaxf(a.z * inv + b.z, 0.f),
                           fmaxf(a.w * inv + b.w, 0.f));
    float4 fw = ((const float4*)fc_w)[lane];
    float p = v.x * fw.x + v.y * fw.y + v.z * fw.z + v.w * fw.w;
#pragma unroll
    for (int off = 16; off >= 1; off >>= 1)
        p += __shfl_down_sync(0xffffffffu, p, off);
    if (lane == 0) {
        float logit = p + fc_b[0];
        out[node] = 1.f / (1.f + __expf(-logit));
    }
}

// ---------------- launch ----------------------------------------------------
extern "C" void kernel_launch(void* const* d_in, const int* in_sizes, int n_in,
                              void* d_out, int out_size) {
    const float* x       = (const float*)d_in[0];
    const int*   ei      = (const int*)  d_in[1];   // int32 or int64 (detected)
    const float* W       = (const float*)d_in[2];
    const float* att_src = (const float*)d_in[3];
    const float* att_dst = (const float*)d_in[4];
    const float* bias    = (const float*)d_in[5];
    const float* fc_w    = (const float*)d_in[6];
    const float* fc_b    = (const float*)d_in[7];
    float* out = (float*)d_out;

    const int N = in_sizes[0] / CIN;
    const int E = in_sizes[1] / 2;
    const int Etot = E + N;

    const int gemm_smem = (CIN * HOUT + CIN * SX_LD) * (int)sizeof(float);
    cudaFuncSetAttribute(gemm_att_kernel,
                         cudaFuncAttributeMaxDynamicSharedMemorySize, gemm_smem);

    detect_kernel<<<1, 64>>>(ei);
    init_kernel<<<4096, 256>>>(N);
    gemm_att_kernel<<<(N + GEMM_ROWS - 1) / GEMM_ROWS, 256, gemm_smem>>>(
        x, W, att_src, att_dst, N);
    edge_passA<<<(Etot + 255) / 256, 256>>>(ei, E, N);
    edge_passB<<<(int)(((size_t)Etot * 32 + 255) / 256), 256>>>(ei, E, N);
    final_kernel<<<(int)(((size_t)N * 32 + 255) / 256), 256>>>(
        bias, fc_w, fc_b, out, N);
}

// round 5
// speedup vs baseline: 1.6045x; 1.6045x over previous
#include <cuda_runtime.h>
#include <math.h>
#include <stdint.h>

// GAT fused pipeline for GNNModel_74801150427817  (round 5: CSR gather +
// parallel hierarchical scan; zero aggregation atomics)
//
//   h = x @ W  (f32x2 FFMA2 SGEMM, W smem-resident) + fused a_src/a_dst dots
//   CSR build: hist over dst -> 3-stage parallel exclusive scan -> scatter src
//   node kernel: warp per dst node, register accumulation of
//       wsum = sum exp(lrelu(asrc[s]+adst[d])),  acc = sum w*h[s]
//     then normalize, +bias, relu, fc dot, sigmoid -> out  (all fused)
//
// Softmax shift-invariance removes the segment-max pass (e bounded ~|7|,
// exp fp32-safe). Shapes fixed: N=500000, E=1500000, C_IN=128, H=4, OUT=32.

#define CIN   128
#define HOUT  128
#define HEADS 4
#define NMAX  500000
#define EMAX  1500000
#define ETOTMAX (EMAX + NMAX)
#define NEG_SLOPE 0.2f
#define SCAN_BS 512
#define MAX_BLKS 1024   // ceil(NMAX/SCAN_BS) = 977 <= 1024

// ---------------- scratch (device globals; no allocation allowed) ----------
__device__ float g_h   [(size_t)NMAX * HOUT];   // 256 MB
__device__ float g_asrc[NMAX * HEADS];
__device__ float g_adst[NMAX * HEADS];
__device__ int   g_cnt [NMAX];
__device__ int   g_off [NMAX];                  // exclusive scan, then bumped
__device__ int   g_bsum[MAX_BLKS];
__device__ int   g_src [ETOTMAX];               // CSR src ids
__device__ int   g_is64;

// ---------------- helpers --------------------------------------------------
__device__ __forceinline__ float lrelu(float v) {
    return v > 0.f ? v : NEG_SLOPE * v;
}
__device__ __forceinline__ int edge_idx(const int* p, int i, int is64) {
    return is64 ? p[2 * i] : p[i];
}
// packed fp32x2 FMA (sm_100+): acc = a*b + acc elementwise, exact fp32
__device__ __forceinline__ void ffma2(unsigned long long& acc,
                                      unsigned long long a,
                                      unsigned long long b) {
    asm("fma.rn.f32x2 %0, %1, %2, %0;" : "+l"(acc) : "l"(a), "l"(b));
}
__device__ __forceinline__ unsigned long long dup2(float v) {
    unsigned long long r;
    asm("mov.b64 %0, {%1, %1};" : "=l"(r) : "f"(v));
    return r;
}
__device__ __forceinline__ float2 unpk(unsigned long long v) {
    float2 r;
    asm("mov.b64 {%0, %1}, %2;" : "=f"(r.x), "=f"(r.y) : "l"(v));
    return r;
}

// ---------------- 0) int32/int64 edge-index detection ----------------------
__global__ void detect_kernel(const int* __restrict__ ei) {
    __shared__ int anynz;
    if (threadIdx.x == 0) anynz = 0;
    __syncthreads();
    // int64 little-endian, values < 2^31 => every odd 32-bit word is zero
    if (ei[2 * threadIdx.x + 1] != 0) atomicOr(&anynz, 1);
    __syncthreads();
    if (threadIdx.x == 0) g_is64 = anynz ? 0 : 1;
}

// ---------------- 1) zero per-node counters ---------------------------------
__global__ void zero_cnt_kernel(int N) {
    int i = blockIdx.x * blockDim.x + threadIdx.x;
    if (i < N) g_cnt[i] = 0;
}

// ---------------- 2) histogram over dst nodes (incl. self-loops) ------------
__global__ void hist_kernel(const int* __restrict__ ei, int E, int N) {
    int i = blockIdx.x * blockDim.x + threadIdx.x;
    int Etot = E + N;
    if (i >= Etot) return;
    const int is64 = g_is64;
    int d = (i < E) ? edge_idx(ei, E + i, is64) : (i - E);
    atomicAdd(&g_cnt[d], 1);
}

// ---------------- 3) parallel exclusive scan (3 stages) ---------------------
// A: per-block exclusive scan of g_cnt -> g_off, block totals -> g_bsum
__global__ __launch_bounds__(SCAN_BS)
void scanA_kernel(int N) {
    __shared__ int sh[SCAN_BS];
    int t = threadIdx.x;
    int i = blockIdx.x * SCAN_BS + t;
    int c = (i < N) ? g_cnt[i] : 0;
    sh[t] = c;
    __syncthreads();
    int excl = 0;
    // Hillis-Steele inclusive scan, then shift
    for (int off = 1; off < SCAN_BS; off <<= 1) {
        int v = (t >= off) ? sh[t - off] : 0;
        __syncthreads();
        sh[t] += v;
        __syncthreads();
    }
    excl = sh[t] - c;
    if (i < N) g_off[i] = excl;
    if (t == SCAN_BS - 1) g_bsum[blockIdx.x] = sh[t];
}

// B: single-block exclusive scan of block sums (nb <= 1024)
__global__ __launch_bounds__(MAX_BLKS)
void scanB_kernel(int nb) {
    __shared__ int sh[MAX_BLKS];
    int t = threadIdx.x;
    int c = (t < nb) ? g_bsum[t] : 0;
    sh[t] = c;
    __syncthreads();
    for (int off = 1; off < MAX_BLKS; off <<= 1) {
        int v = (t >= off) ? sh[t - off] : 0;
        __syncthreads();
        sh[t] += v;
        __syncthreads();
    }
    if (t < nb) g_bsum[t] = sh[t] - c;   // exclusive
}

// C: add block prefix
__global__ __launch_bounds__(SCAN_BS)
void scanC_kernel(int N) {
    int i = blockIdx.x * SCAN_BS + threadIdx.x;
    if (i < N) g_off[i] += g_bsum[blockIdx.x];
}

// ---------------- 4) scatter src ids into CSR slots -------------------------
// bumps g_off[d]; afterwards g_off[d] == segment end == start of d+1
__global__ void scatter_kernel(const int* __restrict__ ei, int E, int N) {
    int i = blockIdx.x * blockDim.x + threadIdx.x;
    int Etot = E + N;
    if (i >= Etot) return;
    const int is64 = g_is64;
    int s, d;
    if (i < E) { s = edge_idx(ei, i, is64); d = edge_idx(ei, E + i, is64); }
    else       { s = d = i - E; }
    int pos = atomicAdd(&g_off[d], 1);
    g_src[pos] = s;
}

// ---------------- 5) SGEMM h = x @ W (f32x2) + fused attention dots ---------
// 256 threads, 64-row tile, full 128 cols, K=128 single shot.
// smem: W resident [128][128] (64KB) + x transposed [128][66] (~34KB)
#define GEMM_ROWS 64
#define SX_LD 66   // even => 8B-aligned row-pair loads

__global__ __launch_bounds__(256, 2)
void gemm_att_kernel(const float* __restrict__ x,
                     const float* __restrict__ W,
                     const float* __restrict__ att_src,
                     const float* __restrict__ att_dst,
                     int N) {
    extern __shared__ float smem[];
    float* sW = smem;                 // [k*128 + c]
    float* sX = smem + CIN * HOUT;    // transposed [k*SX_LD + r]

    const int t = threadIdx.x;
    const int block_row = blockIdx.x * GEMM_ROWS;

    for (int i = t; i < CIN * HOUT / 4; i += 256)
        ((float4*)sW)[i] = ((const float4*)W)[i];

    for (int i = t; i < GEMM_ROWS * 32; i += 256) {
        int r  = i >> 5;
        int kq = i & 31;
        int row = block_row + r;
        float4 v = make_float4(0.f, 0.f, 0.f, 0.f);
        if (row < N)
            v = ((const float4*)(x + (size_t)row * CIN))[kq];
        sX[(4 * kq + 0) * SX_LD + r] = v.x;
        sX[(4 * kq + 1) * SX_LD + r] = v.y;
        sX[(4 * kq + 2) * SX_LD + r] = v.z;
        sX[(4 * kq + 3) * SX_LD + r] = v.w;
    }
    __syncthreads();

    const int tx = t & 31;   // cols 4*tx..4*tx+3
    const int ty = t >> 5;   // rows 8*ty..8*ty+7

    unsigned long long acc[4][4];  // [row-pair][col]: rows (2rp, 2rp+1) packed
#pragma unroll
    for (int rp = 0; rp < 4; rp++)
#pragma unroll
        for (int c = 0; c < 4; c++) acc[rp][c] = 0ull;

#pragma unroll 4
    for (int k = 0; k < CIN; k++) {
        float4 b = *(const float4*)&sW[k * HOUT + 4 * tx];
        unsigned long long bb0 = dup2(b.x), bb1 = dup2(b.y),
                           bb2 = dup2(b.z), bb3 = dup2(b.w);
        const unsigned long long* pA =
            (const unsigned long long*)(sX + k * SX_LD + 8 * ty);
#pragma unroll
        for (int rp = 0; rp < 4; rp++) {
            unsigned long long ap = pA[rp];
            ffma2(acc[rp][0], ap, bb0);
            ffma2(acc[rp][1], ap, bb1);
            ffma2(acc[rp][2], ap, bb2);
            ffma2(acc[rp][3], ap, bb3);
        }
    }

    float4 avs = ((const float4*)att_src)[tx];
    float4 avd = ((const float4*)att_dst)[tx];
#pragma unroll
    for (int rp = 0; rp < 4; rp++) {
        float2 c0 = unpk(acc[rp][0]), c1 = unpk(acc[rp][1]);
        float2 c2 = unpk(acc[rp][2]), c3 = unpk(acc[rp][3]);
#pragma unroll
        for (int half = 0; half < 2; half++) {
            float v0 = half ? c0.y : c0.x;
            float v1 = half ? c1.y : c1.x;
            float v2 = half ? c2.y : c2.x;
            float v3 = half ? c3.y : c3.x;
            int row = block_row + 8 * ty + 2 * rp + half;
            float ps = v0 * avs.x + v1 * avs.y + v2 * avs.z + v3 * avs.w;
            float pd = v0 * avd.x + v1 * avd.y + v2 * avd.z + v3 * avd.w;
#pragma unroll
            for (int off = 4; off >= 1; off >>= 1) {
                ps += __shfl_down_sync(0xffffffffu, ps, off, 8);
                pd += __shfl_down_sync(0xffffffffu, pd, off, 8);
            }
            if (row < N) {
                ((float4*)(g_h + (size_t)row * HOUT))[tx] =
                    make_float4(v0, v1, v2, v3);
                if ((tx & 7) == 0) {
                    int head = tx >> 3;
                    g_asrc[row * HEADS + head] = ps;
                    g_adst[row * HEADS + head] = pd;
                }
            }
        }
    }
}

// ---------------- 6) node kernel: gather + softmax + epilogue, all fused ----
// one warp per dst node; lane owns 4 channels (float4); head = lane>>3
__global__ __launch_bounds__(256)
void node_kernel(const float* __restrict__ bias,
                 const float* __restrict__ fc_w,
                 const float* __restrict__ fc_b,
                 float* __restrict__ out, int N) {
    int d    = (blockIdx.x * blockDim.x + threadIdx.x) >> 5;
    int lane = threadIdx.x & 31;
    if (d >= N) return;
    int head = lane >> 3;

    int end   = g_off[d];                       // post-scatter: segment end
    int start = (d == 0) ? 0 : g_off[d - 1];    // previous segment end

    float ad = g_adst[d * HEADS + head];
    float wsum = 0.f;
    float4 acc = make_float4(0.f, 0.f, 0.f, 0.f);

    for (int base = start; base < end; base += 32) {
        int m = end - base;
        int sj = (lane < m) ? g_src[base + lane] : 0;
        int iters = min(m, 32);
        for (int j = 0; j < iters; j++) {
            int s = __shfl_sync(0xffffffffu, sj, j);
            float as = g_asrc[s * HEADS + head];
            float wl = __expf(lrelu(as + ad));
            float4 hv = ((const float4*)(g_h + (size_t)s * HOUT))[lane];
            wsum += wl;
            acc.x = fmaf(hv.x, wl, acc.x);
            acc.y = fmaf(hv.y, wl, acc.y);
            acc.z = fmaf(hv.z, wl, acc.z);
            acc.w = fmaf(hv.w, wl, acc.w);
        }
    }

    float inv = 1.f / wsum;                     // wsum > 0 (self-loop exists)
    float4 b = ((const float4*)bias)[lane];
    float4 v = make_float4(fmaxf(acc.x * inv + b.x, 0.f),
                           fmaxf(acc.y * inv + b.y, 0.f),
                           fmaxf(acc.z * inv + b.z, 0.f),
                           fmaxf(acc.w * inv + b.w, 0.f));
    float4 fw = ((const float4*)fc_w)[lane];
    float p = v.x * fw.x + v.y * fw.y + v.z * fw.z + v.w * fw.w;
#pragma unroll
    for (int off = 16; off >= 1; off >>= 1)
        p += __shfl_down_sync(0xffffffffu, p, off);
    if (lane == 0) {
        float logit = p + fc_b[0];
        out[d] = 1.f / (1.f + __expf(-logit));
    }
}

// ---------------- launch ----------------------------------------------------
extern "C" void kernel_launch(void* const* d_in, const int* in_sizes, int n_in,
                              void* d_out, int out_size) {
    const float* x       = (const float*)d_in[0];
    const int*   ei      = (const int*)  d_in[1];   // int32 or int64 (detected)
    const float* W       = (const float*)d_in[2];
    const float* att_src = (const float*)d_in[3];
    const float* att_dst = (const float*)d_in[4];
    const float* bias    = (const float*)d_in[5];
    const float* fc_w    = (const float*)d_in[6];
    const float* fc_b    = (const float*)d_in[7];
    float* out = (float*)d_out;

    const int N = in_sizes[0] / CIN;
    const int E = in_sizes[1] / 2;
    const int Etot = E + N;
    const int nb = (N + SCAN_BS - 1) / SCAN_BS;

    const int gemm_smem = (CIN * HOUT + CIN * SX_LD) * (int)sizeof(float);
    cudaFuncSetAttribute(gemm_att_kernel,
                         cudaFuncAttributeMaxDynamicSharedMemorySize, gemm_smem);

    detect_kernel<<<1, 64>>>(ei);
    zero_cnt_kernel<<<(N + 255) / 256, 256>>>(N);
    hist_kernel<<<(Etot + 255) / 256, 256>>>(ei, E, N);
    scanA_kernel<<<nb, SCAN_BS>>>(N);
    scanB_kernel<<<1, MAX_BLKS>>>(nb);
    scanC_kernel<<<nb, SCAN_BS>>>(N);
    scatter_kernel<<<(Etot + 255) / 256, 256>>>(ei, E, N);
    gemm_att_kernel<<<(N + GEMM_ROWS - 1) / GEMM_ROWS, 256, gemm_smem>>>(
        x, W, att_src, att_dst, N);
    node_kernel<<<(int)(((size_t)N * 32 + 255) / 256), 256>>>(
        bias, fc_w, fc_b, out, N);
}

// round 8
// speedup vs baseline: 1.7299x; 1.0782x over previous
#include <cuda_runtime.h>
#include <cuda_fp16.h>
#include <mma.h>
#include <math.h>
#include <stdint.h>

// GAT fused pipeline for GNNModel_74801150427817  (round 8 = round 7 resubmit,
// audited)
//   - GEMM on tensor cores: WMMA 16x16x16 fp16 inputs, fp32 accumulate
//   - h stored fp16 (halves the node-gather traffic)
//   - CSR gather aggregation (zero atomics), fused softmax+epilogue
//
//   h = x @ W  (wmma fp16/fp32) + fused a_src/a_dst dots     -> g_h (fp16)
//   CSR build: hist over dst -> 3-stage parallel scan -> scatter src ids
//   node kernel: warp per dst node, fp32 register accumulation of
//       wsum = sum exp(lrelu(asrc[s]+adst[d])),  acc = sum w*h[s]
//     then normalize, +bias, relu, fc dot, sigmoid -> out
//
// Softmax shift-invariance removes the segment-max pass (e bounded ~|7|,
// exp fp32-safe). Shapes fixed: N=500000, E=1500000, C_IN=128, H=4, OUT=32.

#define CIN   128
#define HOUT  128
#define HEADS 4
#define NMAX  500000
#define EMAX  1500000
#define ETOTMAX (EMAX + NMAX)
#define NEG_SLOPE 0.2f
#define SCAN_BS 512
#define MAX_BLKS 1024   // ceil(NMAX/SCAN_BS) = 977 <= 1024

using namespace nvcuda;

// ---------------- scratch (device globals; no allocation allowed) ----------
__device__ __half g_h [(size_t)NMAX * HOUT];    // 128 MB (fp16 h)
__device__ float g_asrc[NMAX * HEADS];
__device__ float g_adst[NMAX * HEADS];
__device__ int   g_cnt [NMAX];
__device__ int   g_off [NMAX];                  // exclusive scan, then bumped
__device__ int   g_bsum[MAX_BLKS];
__device__ int   g_src [ETOTMAX];               // CSR src ids
__device__ int   g_is64;

// ---------------- helpers --------------------------------------------------
__device__ __forceinline__ float lrelu(float v) {
    return v > 0.f ? v : NEG_SLOPE * v;
}
__device__ __forceinline__ int edge_idx(const int* p, int i, int is64) {
    return is64 ? p[2 * i] : p[i];
}
__device__ __forceinline__ uint2 pack4h(float a, float b, float c, float d) {
    __half2 p0 = __floats2half2_rn(a, b);
    __half2 p1 = __floats2half2_rn(c, d);
    uint2 r;
    r.x = *(unsigned int*)&p0;
    r.y = *(unsigned int*)&p1;
    return r;
}

// ---------------- 0) int32/int64 edge-index detection ----------------------
__global__ void detect_kernel(const int* __restrict__ ei) {
    __shared__ int anynz;
    if (threadIdx.x == 0) anynz = 0;
    __syncthreads();
    // int64 little-endian, values < 2^31 => every odd 32-bit word is zero
    if (ei[2 * threadIdx.x + 1] != 0) atomicOr(&anynz, 1);
    __syncthreads();
    if (threadIdx.x == 0) g_is64 = anynz ? 0 : 1;
}

// ---------------- 1) zero per-node counters ---------------------------------
__global__ void zero_cnt_kernel(int N) {
    int i = blockIdx.x * blockDim.x + threadIdx.x;
    if (i < N) g_cnt[i] = 0;
}

// ---------------- 2) histogram over dst nodes (incl. self-loops) ------------
__global__ void hist_kernel(const int* __restrict__ ei, int E, int N) {
    int i = blockIdx.x * blockDim.x + threadIdx.x;
    int Etot = E + N;
    if (i >= Etot) return;
    const int is64 = g_is64;
    int d = (i < E) ? edge_idx(ei, E + i, is64) : (i - E);
    atomicAdd(&g_cnt[d], 1);
}

// ---------------- 3) parallel exclusive scan (3 stages) ---------------------
__global__ __launch_bounds__(SCAN_BS)
void scanA_kernel(int N) {
    __shared__ int sh[SCAN_BS];
    int t = threadIdx.x;
    int i = blockIdx.x * SCAN_BS + t;
    int c = (i < N) ? g_cnt[i] : 0;
    sh[t] = c;
    __syncthreads();
    for (int off = 1; off < SCAN_BS; off <<= 1) {
        int v = (t >= off) ? sh[t - off] : 0;
        __syncthreads();
        sh[t] += v;
        __syncthreads();
    }
    if (i < N) g_off[i] = sh[t] - c;           // exclusive
    if (t == SCAN_BS - 1) g_bsum[blockIdx.x] = sh[t];
}

__global__ __launch_bounds__(MAX_BLKS)
void scanB_kernel(int nb) {
    __shared__ int sh[MAX_BLKS];
    int t = threadIdx.x;
    int c = (t < nb) ? g_bsum[t] : 0;
    sh[t] = c;
    __syncthreads();
    for (int off = 1; off < MAX_BLKS; off <<= 1) {
        int v = (t >= off) ? sh[t - off] : 0;
        __syncthreads();
        sh[t] += v;
        __syncthreads();
    }
    if (t < nb) g_bsum[t] = sh[t] - c;         // exclusive
}

__global__ __launch_bounds__(SCAN_BS)
void scanC_kernel(int N) {
    int i = blockIdx.x * SCAN_BS + threadIdx.x;
    if (i < N) g_off[i] += g_bsum[blockIdx.x];
}

// ---------------- 4) scatter src ids into CSR slots -------------------------
// bumps g_off[d]; afterwards g_off[d] == segment end == start of d+1
__global__ void scatter_kernel(const int* __restrict__ ei, int E, int N) {
    int i = blockIdx.x * blockDim.x + threadIdx.x;
    int Etot = E + N;
    if (i >= Etot) return;
    const int is64 = g_is64;
    int s, d;
    if (i < E) { s = edge_idx(ei, i, is64); d = edge_idx(ei, E + i, is64); }
    else       { s = d = i - E; }
    int pos = atomicAdd(&g_off[d], 1);
    g_src[pos] = s;
}

// ---------------- 5) WMMA GEMM h = x @ W + fused attention dots -------------
// 256 threads (8 warps), 64-row tile, all 128 cols, K=128.
// Phase 1 smem: W fp16 [128][128] (32768B) + x fp16 [64][XLD] (17408B)
// Phase 2 smem (overlaid): out fp32 [64][OLD] (34816B) -- fits in phase-1 size
#define GEMM_ROWS 64
#define XLD 136   // fp16 elems/row: 128 + 8 pad (ld mult of 8 halves = 16B)
#define OLD 136   // fp32 elems/row (ld mult of 4 floats = 16B)

__global__ __launch_bounds__(256)
void gemm_att_kernel(const float* __restrict__ x,
                     const float* __restrict__ W,
                     const float* __restrict__ att_src,
                     const float* __restrict__ att_dst,
                     int N) {
    extern __shared__ char smem[];
    __half* sW = (__half*)smem;                  // [k][n], ld=128
    __half* sX = sW + CIN * HOUT;                // [m][k], ld=XLD
    float*  sO = (float*)smem;                   // overlaid after k-loop

    const int t = threadIdx.x;
    const int block_row = blockIdx.x * GEMM_ROWS;

    // W -> fp16 smem (16384 halves)
    for (int i = t; i < CIN * HOUT / 4; i += 256) {
        float4 v = ((const float4*)W)[i];
        ((uint2*)sW)[i] = pack4h(v.x, v.y, v.z, v.w);
    }
    // x tile -> fp16 smem
    for (int i = t; i < GEMM_ROWS * 32; i += 256) {
        int r  = i >> 5;
        int kq = i & 31;
        int row = block_row + r;
        float4 v = make_float4(0.f, 0.f, 0.f, 0.f);
        if (row < N)
            v = ((const float4*)(x + (size_t)row * CIN))[kq];
        *(uint2*)(sX + r * XLD + 4 * kq) = pack4h(v.x, v.y, v.z, v.w);
    }
    __syncthreads();

    // warp w: rows m0..m0+15, cols nb..nb+63 (4 accumulator tiles)
    const int w  = t >> 5;
    const int m0 = (w & 3) * 16;
    const int nb = (w >> 2) * 64;

    wmma::fragment<wmma::matrix_a, 16, 16, 16, __half, wmma::row_major> fa;
    wmma::fragment<wmma::matrix_b, 16, 16, 16, __half, wmma::row_major> fb;
    wmma::fragment<wmma::accumulator, 16, 16, 16, float> facc[4];
#pragma unroll
    for (int j = 0; j < 4; j++) wmma::fill_fragment(facc[j], 0.f);

#pragma unroll
    for (int k0 = 0; k0 < CIN; k0 += 16) {
        wmma::load_matrix_sync(fa, sX + m0 * XLD + k0, XLD);
#pragma unroll
        for (int j = 0; j < 4; j++) {
            wmma::load_matrix_sync(fb, sW + k0 * HOUT + nb + j * 16, HOUT);
            wmma::mma_sync(facc[j], fa, fb, facc[j]);
        }
    }

    __syncthreads();   // k-loop smem dead -> overlay as fp32 out
#pragma unroll
    for (int j = 0; j < 4; j++)
        wmma::store_matrix_sync(sO + m0 * OLD + nb + j * 16, facc[j], OLD,
                                wmma::mem_row_major);
    __syncthreads();

    // epilogue: fused attention dots + fp16 h store.
    // warp ty owns rows 8ty..8ty+7; lane tx owns cols 4tx..4tx+3; head=tx>>3
    const int tx = t & 31;
    const int ty = t >> 5;
    float4 avs = ((const float4*)att_src)[tx];
    float4 avd = ((const float4*)att_dst)[tx];
#pragma unroll
    for (int r8 = 0; r8 < 8; r8++) {
        int lr  = 8 * ty + r8;
        int row = block_row + lr;
        float4 v = *(const float4*)(sO + lr * OLD + 4 * tx);
        float ps = v.x * avs.x + v.y * avs.y + v.z * avs.z + v.w * avs.w;
        float pd = v.x * avd.x + v.y * avd.y + v.z * avd.z + v.w * avd.w;
#pragma unroll
        for (int off = 4; off >= 1; off >>= 1) {
            ps += __shfl_down_sync(0xffffffffu, ps, off, 8);
            pd += __shfl_down_sync(0xffffffffu, pd, off, 8);
        }
        if (row < N) {
            ((uint2*)(g_h + (size_t)row * HOUT))[tx] =
                pack4h(v.x, v.y, v.z, v.w);
            if ((tx & 7) == 0) {
                int head = tx >> 3;
                g_asrc[row * HEADS + head] = ps;
                g_adst[row * HEADS + head] = pd;
            }
        }
    }
}

// ---------------- 6) node kernel: gather + softmax + epilogue, all fused ----
// one warp per dst node; lane owns 4 channels (uint2 = 2 half2); head = lane>>3
__global__ __launch_bounds__(256)
void node_kernel(const float* __restrict__ bias,
                 const float* __restrict__ fc_w,
                 const float* __restrict__ fc_b,
                 float* __restrict__ out, int N) {
    int d    = (blockIdx.x * blockDim.x + threadIdx.x) >> 5;
    int lane = threadIdx.x & 31;
    if (d >= N) return;
    int head = lane >> 3;

    int end   = g_off[d];                       // post-scatter: segment end
    int start = (d == 0) ? 0 : g_off[d - 1];    // previous segment end

    float ad = g_adst[d * HEADS + head];
    float wsum = 0.f;
    float4 acc = make_float4(0.f, 0.f, 0.f, 0.f);

    for (int base = start; base < end; base += 32) {
        int m = end - base;
        int sj = (lane < m) ? g_src[base + lane] : 0;
        int iters = min(m, 32);
        for (int j = 0; j < iters; j++) {
            int s = __shfl_sync(0xffffffffu, sj, j);
            float as = g_asrc[s * HEADS + head];
            float wl = __expf(lrelu(as + ad));
            uint2 pk = ((const uint2*)(g_h + (size_t)s * HOUT))[lane];
            float2 h0 = __half22float2(*(__half2*)&pk.x);
            float2 h1 = __half22float2(*(__half2*)&pk.y);
            wsum += wl;
            acc.x = fmaf(h0.x, wl, acc.x);
            acc.y = fmaf(h0.y, wl, acc.y);
            acc.z = fmaf(h1.x, wl, acc.z);
            acc.w = fmaf(h1.y, wl, acc.w);
        }
    }

    float inv = 1.f / wsum;                     // wsum > 0 (self-loop exists)
    float4 b = ((const float4*)bias)[lane];
    float4 v = make_float4(fmaxf(acc.x * inv + b.x, 0.f),
                           fmaxf(acc.y * inv + b.y, 0.f),
                           fmaxf(acc.z * inv + b.z, 0.f),
                           fmaxf(acc.w * inv + b.w, 0.f));
    float4 fw = ((const float4*)fc_w)[lane];
    float p = v.x * fw.x + v.y * fw.y + v.z * fw.z + v.w * fw.w;
#pragma unroll
    for (int off = 16; off >= 1; off >>= 1)
        p += __shfl_down_sync(0xffffffffu, p, off);
    if (lane == 0) {
        float logit = p + fc_b[0];
        out[d] = 1.f / (1.f + __expf(-logit));
    }
}

// ---------------- launch ----------------------------------------------------
extern "C" void kernel_launch(void* const* d_in, const int* in_sizes, int n_in,
                              void* d_out, int out_size) {
    const float* x       = (const float*)d_in[0];
    const int*   ei      = (const int*)  d_in[1];   // int32 or int64 (detected)
    const float* W       = (const float*)d_in[2];
    const float* att_src = (const float*)d_in[3];
    const float* att_dst = (const float*)d_in[4];
    const float* bias    = (const float*)d_in[5];
    const float* fc_w    = (const float*)d_in[6];
    const float* fc_b    = (const float*)d_in[7];
    float* out = (float*)d_out;

    const int N = in_sizes[0] / CIN;
    const int E = in_sizes[1] / 2;
    const int Etot = E + N;
    const int nb = (N + SCAN_BS - 1) / SCAN_BS;

    // phase1: W fp16 (32KB) + x fp16 (64*XLD*2 = 17KB); phase2 overlay fits
    const int gemm_smem = CIN * HOUT * 2 + GEMM_ROWS * XLD * 2;
    cudaFuncSetAttribute(gemm_att_kernel,
                         cudaFuncAttributeMaxDynamicSharedMemorySize, gemm_smem);

    detect_kernel<<<1, 64>>>(ei);
    zero_cnt_kernel<<<(N + 255) / 256, 256>>>(N);
    hist_kernel<<<(Etot + 255) / 256, 256>>>(ei, E, N);
    scanA_kernel<<<nb, SCAN_BS>>>(N);
    scanB_kernel<<<1, MAX_BLKS>>>(nb);
    scanC_kernel<<<nb, SCAN_BS>>>(N);
    scatter_kernel<<<(Etot + 255) / 256, 256>>>(ei, E, N);
    gemm_att_kernel<<<(N + GEMM_ROWS - 1) / GEMM_ROWS, 256, gemm_smem>>>(
        x, W, att_src, att_dst, N);
    node_kernel<<<(int)(((size_t)N * 32 + 255) / 256), 256>>>(
        bias, fc_w, fc_b, out, N);
}

// round 14
// speedup vs baseline: 2.3184x; 1.3402x over previous
#include <cuda_runtime.h>
#include <cuda_fp16.h>
#include <mma.h>
#include <math.h>
#include <stdint.h>

// GAT fused pipeline for GNNModel_74801150427817  (round 14 = R13 resubmit)
//   - GEMM tile 128 rows/block (halves per-block W smem-load traffic)
//   - W converted to fp16 ONCE, GEMM loads fp16 W directly
//   - sW/sX padded to ld=136 to break 128B-periodic LDSM bank conflicts
//   - node kernel: 2-way edge ILP (dual accumulators)
//   - WMMA fp16/fp32 GEMM, fp16 h storage, CSR gather, no aggregation atomics
//   - gemm at launch index 3 = ncu capture slot
//
// Softmax shift-invariance removes the segment-max pass. Shapes fixed:
// N=500000, E=1500000, C_IN=128, H=4, OUT=32.

#define CIN   128
#define HOUT  128
#define HEADS 4
#define NMAX  500000
#define EMAX  1500000
#define ETOTMAX (EMAX + NMAX)
#define NEG_SLOPE 0.2f
#define SCAN_BS 512
#define MAX_BLKS 1024   // ceil(NMAX/SCAN_BS) = 977 <= 1024

using namespace nvcuda;

// ---------------- scratch (device globals; no allocation allowed) ----------
__device__ __half g_h [(size_t)NMAX * HOUT];    // 128 MB (fp16 h)
__device__ __half g_W16[CIN * HOUT];            // fp16 W (one-shot convert)
__device__ float g_asrc[NMAX * HEADS];
__device__ float g_adst[NMAX * HEADS];
__device__ int   g_cnt [NMAX];
__device__ int   g_off [NMAX];                  // exclusive scan, then bumped
__device__ int   g_bsum[MAX_BLKS];
__device__ int   g_src [ETOTMAX];               // CSR src ids
__device__ int   g_is64;

// ---------------- helpers --------------------------------------------------
__device__ __forceinline__ float lrelu(float v) {
    return v > 0.f ? v : NEG_SLOPE * v;
}
__device__ __forceinline__ int edge_idx(const int* p, int i, int is64) {
    return is64 ? p[2 * i] : p[i];
}
__device__ __forceinline__ uint2 pack4h(float a, float b, float c, float d) {
    __half2 p0 = __floats2half2_rn(a, b);
    __half2 p1 = __floats2half2_rn(c, d);
    uint2 r;
    r.x = *(unsigned int*)&p0;
    r.y = *(unsigned int*)&p1;
    return r;
}

// ---------------- 0) int32/int64 edge-index detection ----------------------
__global__ void detect_kernel(const int* __restrict__ ei) {
    __shared__ int anynz;
    if (threadIdx.x == 0) anynz = 0;
    __syncthreads();
    // int64 little-endian, values < 2^31 => every odd 32-bit word is zero
    if (ei[2 * threadIdx.x + 1] != 0) atomicOr(&anynz, 1);
    __syncthreads();
    if (threadIdx.x == 0) g_is64 = anynz ? 0 : 1;
}

// ---------------- 0b) one-shot W -> fp16 ------------------------------------
__global__ void wconv_kernel(const float* __restrict__ W) {
    int i = blockIdx.x * blockDim.x + threadIdx.x;   // uint2 index (4 halves)
    if (i < CIN * HOUT / 4) {
        float4 v = ((const float4*)W)[i];
        ((uint2*)g_W16)[i] = pack4h(v.x, v.y, v.z, v.w);
    }
}

// ---------------- 1) zero per-node counters ---------------------------------
__global__ void zero_cnt_kernel(int N) {
    int i = blockIdx.x * blockDim.x + threadIdx.x;
    if (i < N) g_cnt[i] = 0;
}

// ---------------- 2) histogram over dst nodes (incl. self-loops) ------------
__global__ void hist_kernel(const int* __restrict__ ei, int E, int N) {
    int i = blockIdx.x * blockDim.x + threadIdx.x;
    int Etot = E + N;
    if (i >= Etot) return;
    const int is64 = g_is64;
    int d = (i < E) ? edge_idx(ei, E + i, is64) : (i - E);
    atomicAdd(&g_cnt[d], 1);
}

// ---------------- 3) parallel exclusive scan (3 stages) ---------------------
__global__ __launch_bounds__(SCAN_BS)
void scanA_kernel(int N) {
    __shared__ int sh[SCAN_BS];
    int t = threadIdx.x;
    int i = blockIdx.x * SCAN_BS + t;
    int c = (i < N) ? g_cnt[i] : 0;
    sh[t] = c;
    __syncthreads();
    for (int off = 1; off < SCAN_BS; off <<= 1) {
        int v = (t >= off) ? sh[t - off] : 0;
        __syncthreads();
        sh[t] += v;
        __syncthreads();
    }
    if (i < N) g_off[i] = sh[t] - c;           // exclusive
    if (t == SCAN_BS - 1) g_bsum[blockIdx.x] = sh[t];
}

__global__ __launch_bounds__(MAX_BLKS)
void scanB_kernel(int nb) {
    __shared__ int sh[MAX_BLKS];
    int t = threadIdx.x;
    int c = (t < nb) ? g_bsum[t] : 0;
    sh[t] = c;
    __syncthreads();
    for (int off = 1; off < MAX_BLKS; off <<= 1) {
        int v = (t >= off) ? sh[t - off] : 0;
        __syncthreads();
        sh[t] += v;
        __syncthreads();
    }
    if (t < nb) g_bsum[t] = sh[t] - c;         // exclusive
}

__global__ __launch_bounds__(SCAN_BS)
void scanC_kernel(int N) {
    int i = blockIdx.x * SCAN_BS + threadIdx.x;
    if (i < N) g_off[i] += g_bsum[blockIdx.x];
}

// ---------------- 4) scatter src ids into CSR slots -------------------------
// bumps g_off[d]; afterwards g_off[d] == segment end == start of d+1
__global__ void scatter_kernel(const int* __restrict__ ei, int E, int N) {
    int i = blockIdx.x * blockDim.x + threadIdx.x;
    int Etot = E + N;
    if (i >= Etot) return;
    const int is64 = g_is64;
    int s, d;
    if (i < E) { s = edge_idx(ei, i, is64); d = edge_idx(ei, E + i, is64); }
    else       { s = d = i - E; }
    int pos = atomicAdd(&g_off[d], 1);
    g_src[pos] = s;
}

// ---------------- 5) WMMA GEMM h = x @ W + fused attention dots -------------
// 256 threads (8 warps), 128-row tile, all 128 cols, K=128.
// warp w: rows 16w..16w+15, all 8 col-tiles.
// Phase 1 smem: W fp16 [128][WLD] (34816B) + x fp16 [128][XLD] (34816B)
// Phase 2 smem (overlaid): out fp32 [128][OLD] (69632B) -- exact fit
#define GEMM_ROWS 128
#define WLD 136   // 128 + 8 pad -> 272B rows, breaks 128B-period conflicts
#define XLD 136
#define OLD 136   // fp32 elems/row

__global__ __launch_bounds__(256)
void gemm_att_kernel(const float* __restrict__ x,
                     const float* __restrict__ att_src,
                     const float* __restrict__ att_dst,
                     int N) {
    extern __shared__ char smem[];
    __half* sW = (__half*)smem;                  // [k][n], ld=WLD
    __half* sX = sW + CIN * WLD;                 // [m][k], ld=XLD
    float*  sO = (float*)smem;                   // overlaid after k-loop

    const int t = threadIdx.x;
    const int block_row = blockIdx.x * GEMM_ROWS;

    // W fp16 -> smem (padded rows). 128 rows x 32 uint2 per row.
    for (int i = t; i < CIN * 32; i += 256) {
        int k  = i >> 5;
        int cq = i & 31;          // uint2 (4 halves) index in row
        *(uint2*)(sW + k * WLD + 4 * cq) = ((const uint2*)g_W16)[i];
    }
    // x tile -> fp16 smem (128 rows x 32 uint2)
    for (int i = t; i < GEMM_ROWS * 32; i += 256) {
        int r  = i >> 5;
        int kq = i & 31;
        int row = block_row + r;
        float4 v = make_float4(0.f, 0.f, 0.f, 0.f);
        if (row < N)
            v = ((const float4*)(x + (size_t)row * CIN))[kq];
        *(uint2*)(sX + r * XLD + 4 * kq) = pack4h(v.x, v.y, v.z, v.w);
    }
    __syncthreads();

    // warp w: rows m0..m0+15, all 128 cols (8 accumulator tiles)
    const int w  = t >> 5;
    const int m0 = w * 16;

    wmma::fragment<wmma::matrix_a, 16, 16, 16, __half, wmma::row_major> fa;
    wmma::fragment<wmma::matrix_b, 16, 16, 16, __half, wmma::row_major> fb;
    wmma::fragment<wmma::accumulator, 16, 16, 16, float> facc[8];
#pragma unroll
    for (int j = 0; j < 8; j++) wmma::fill_fragment(facc[j], 0.f);

#pragma unroll
    for (int k0 = 0; k0 < CIN; k0 += 16) {
        wmma::load_matrix_sync(fa, sX + m0 * XLD + k0, XLD);
#pragma unroll
        for (int j = 0; j < 8; j++) {
            wmma::load_matrix_sync(fb, sW + k0 * WLD + j * 16, WLD);
            wmma::mma_sync(facc[j], fa, fb, facc[j]);
        }
    }

    __syncthreads();   // k-loop smem dead -> overlay as fp32 out
#pragma unroll
    for (int j = 0; j < 8; j++)
        wmma::store_matrix_sync(sO + m0 * OLD + j * 16, facc[j], OLD,
                                wmma::mem_row_major);
    __syncthreads();

    // epilogue: fused attention dots + fp16 h store.
    // warp ty owns rows 16ty..16ty+15; lane tx owns cols 4tx..4tx+3
    const int tx = t & 31;
    const int ty = t >> 5;
    float4 avs = ((const float4*)att_src)[tx];
    float4 avd = ((const float4*)att_dst)[tx];
#pragma unroll
    for (int r8 = 0; r8 < 16; r8++) {
        int lr  = 16 * ty + r8;
        int row = block_row + lr;
        float4 v = *(const float4*)(sO + lr * OLD + 4 * tx);
        float ps = v.x * avs.x + v.y * avs.y + v.z * avs.z + v.w * avs.w;
        float pd = v.x * avd.x + v.y * avd.y + v.z * avd.z + v.w * avd.w;
#pragma unroll
        for (int off = 4; off >= 1; off >>= 1) {
            ps += __shfl_down_sync(0xffffffffu, ps, off, 8);
            pd += __shfl_down_sync(0xffffffffu, pd, off, 8);
        }
        if (row < N) {
            ((uint2*)(g_h + (size_t)row * HOUT))[tx] =
                pack4h(v.x, v.y, v.z, v.w);
            if ((tx & 7) == 0) {
                int head = tx >> 3;
                g_asrc[row * HEADS + head] = ps;
                g_adst[row * HEADS + head] = pd;
            }
        }
    }
}

// ---------------- 6) node kernel: gather + softmax + epilogue ----------------
// one warp per dst node; lane owns 4 channels; 2-way edge ILP
__global__ __launch_bounds__(256)
void node_kernel(const float* __restrict__ bias,
                 const float* __restrict__ fc_w,
                 const float* __restrict__ fc_b,
                 float* __restrict__ out, int N) {
    int d    = (blockIdx.x * blockDim.x + threadIdx.x) >> 5;
    int lane = threadIdx.x & 31;
    if (d >= N) return;
    int head = lane >> 3;

    int end   = g_off[d];                       // post-scatter: segment end
    int start = (d == 0) ? 0 : g_off[d - 1];    // previous segment end

    float ad = g_adst[d * HEADS + head];
    float wsum0 = 0.f, wsum1 = 0.f;
    float4 acc0 = make_float4(0.f, 0.f, 0.f, 0.f);
    float4 acc1 = make_float4(0.f, 0.f, 0.f, 0.f);

    for (int base = start; base < end; base += 32) {
        int m = end - base;
        int sj = (lane < m) ? g_src[base + lane] : 0;
        int iters = min(m, 32);
        int j = 0;
        for (; j + 1 < iters; j += 2) {           // dual-issue: 2 edges/iter
            int s0 = __shfl_sync(0xffffffffu, sj, j);
            int s1 = __shfl_sync(0xffffffffu, sj, j + 1);
            float as0 = g_asrc[s0 * HEADS + head];
            float as1 = g_asrc[s1 * HEADS + head];
            uint2 p0 = ((const uint2*)(g_h + (size_t)s0 * HOUT))[lane];
            uint2 p1 = ((const uint2*)(g_h + (size_t)s1 * HOUT))[lane];
            float w0 = __expf(lrelu(as0 + ad));
            float w1 = __expf(lrelu(as1 + ad));
            float2 a0 = __half22float2(*(__half2*)&p0.x);
            float2 b0 = __half22float2(*(__half2*)&p0.y);
            float2 a1 = __half22float2(*(__half2*)&p1.x);
            float2 b1 = __half22float2(*(__half2*)&p1.y);
            wsum0 += w0; wsum1 += w1;
            acc0.x = fmaf(a0.x, w0, acc0.x);
            acc0.y = fmaf(a0.y, w0, acc0.y);
            acc0.z = fmaf(b0.x, w0, acc0.z);
            acc0.w = fmaf(b0.y, w0, acc0.w);
            acc1.x = fmaf(a1.x, w1, acc1.x);
            acc1.y = fmaf(a1.y, w1, acc1.y);
            acc1.z = fmaf(b1.x, w1, acc1.z);
            acc1.w = fmaf(b1.y, w1, acc1.w);
        }
        if (j < iters) {                          // tail edge
            int s0 = __shfl_sync(0xffffffffu, sj, j);
            float as0 = g_asrc[s0 * HEADS + head];
            uint2 p0 = ((const uint2*)(g_h + (size_t)s0 * HOUT))[lane];
            float w0 = __expf(lrelu(as0 + ad));
            float2 a0 = __half22float2(*(__half2*)&p0.x);
            float2 b0 = __half22float2(*(__half2*)&p0.y);
            wsum0 += w0;
            acc0.x = fmaf(a0.x, w0, acc0.x);
            acc0.y = fmaf(a0.y, w0, acc0.y);
            acc0.z = fmaf(b0.x, w0, acc0.z);
            acc0.w = fmaf(b0.y, w0, acc0.w);
        }
    }
    float wsum = wsum0 + wsum1;
    float4 acc = make_float4(acc0.x + acc1.x, acc0.y + acc1.y,
                             acc0.z + acc1.z, acc0.w + acc1.w);

    float inv = 1.f / wsum;                     // wsum > 0 (self-loop exists)
    float4 b = ((const float4*)bias)[lane];
    float4 v = make_float4(fmaxf(acc.x * inv + b.x, 0.f),
                           fmaxf(acc.y * inv + b.y, 0.f),
                           fmaxf(acc.z * inv + b.z, 0.f),
                           fmaxf(acc.w * inv + b.w, 0.f));
    float4 fw = ((const float4*)fc_w)[lane];
    float p = v.x * fw.x + v.y * fw.y + v.z * fw.z + v.w * fw.w;
#pragma unroll
    for (int off = 16; off >= 1; off >>= 1)
        p += __shfl_down_sync(0xffffffffu, p, off);
    if (lane == 0) {
        float logit = p + fc_b[0];
        out[d] = 1.f / (1.f + __expf(-logit));
    }
}

// ---------------- launch ----------------------------------------------------
// gemm_att_kernel deliberately at launch index 3 — the ncu capture slot
// (empirically launch #3 across R2/R5/R8) — so the next successful capture
// profiles the GEMM. gemm depends only on wconv; the CSR pipeline
// (hist..scatter) is independent and runs after.
extern "C" void kernel_launch(void* const* d_in, const int* in_sizes, int n_in,
                              void* d_out, int out_size) {
    const float* x       = (const float*)d_in[0];
    const int*   ei      = (const int*)  d_in[1];   // int32 or int64 (detected)
    const float* W       = (const float*)d_in[2];
    const float* att_src = (const float*)d_in[3];
    const float* att_dst = (const float*)d_in[4];
    const float* bias    = (const float*)d_in[5];
    const float* fc_w    = (const float*)d_in[6];
    const float* fc_b    = (const float*)d_in[7];
    float* out = (float*)d_out;

    const int N = in_sizes[0] / CIN;
    const int E = in_sizes[1] / 2;
    const int Etot = E + N;
    const int nb = (N + SCAN_BS - 1) / SCAN_BS;

    // phase1: W fp16 (128*WLD*2) + x fp16 (128*XLD*2) = 69632B;
    // phase2 overlay sO (128*OLD*4) = 69632B -- exact fit
    const int gemm_smem = CIN * WLD * 2 + GEMM_ROWS * XLD * 2;
    cudaFuncSetAttribute(gemm_att_kernel,
                         cudaFuncAttributeMaxDynamicSharedMemorySize, gemm_smem);

    detect_kernel<<<1, 64>>>(ei);                                   // 0
    wconv_kernel<<<(CIN * HOUT / 4 + 255) / 256, 256>>>(W);         // 1
    zero_cnt_kernel<<<(N + 255) / 256, 256>>>(N);                   // 2
    gemm_att_kernel<<<(N + GEMM_ROWS - 1) / GEMM_ROWS, 256,         // 3 <- ncu
                      gemm_smem>>>(x, att_src, att_dst, N);
    hist_kernel<<<(Etot + 255) / 256, 256>>>(ei, E, N);             // 4
    scanA_kernel<<<nb, SCAN_BS>>>(N);                               // 5
    scanB_kernel<<<1, MAX_BLKS>>>(nb);                              // 6
    scanC_kernel<<<nb, SCAN_BS>>>(N);                               // 7
    scatter_kernel<<<(Etot + 255) / 256, 256>>>(ei, E, N);          // 8
    node_kernel<<<(int)(((size_t)N * 32 + 255) / 256), 256>>>(      // 9
        bias, fc_w, fc_b, out, N);
}